// round 5
// baseline (speedup 1.0000x reference)
#include <cuda_runtime.h>
#include <cuda_bf16.h>
#include <cstdint>

// ============================ problem constants ============================
#define HDIM 256
#define SDIM 512
#define BDIM 2048
#define CDIM 10
#define BT   16                 // batch columns per CTA (two groups of 8)
#define NCTA (BDIM / BT)        // 128
#define NTHR 256                // 8 warps, each owns m=32 (two m16 tiles)

// ============================ SMEM layout (bytes) ==========================
// Wlo fragments: [8 warps][2 mtiles][16 k][32 lanes][16B] = 131072 B
#define WLO_OFF 0
#define WLO_SZ  131072
// h tiles: [group(2)][parity(2)][hi/lo(2)] of [k=256][n=8] bf16, 16B rows
#define HT_SZ   4096
#define HB_OFF  WLO_SZ                    // 131072
#define HB_SZ   (8 * HT_SZ)               // 32768
// x staged [n=16][t=512] fp32, row pad 516 floats
#define XROW    516
#define XS_OFF  (HB_OFF + HB_SZ)          // 163840
#define XS_SZ   (BT * XROW * 4)           // 33024
#define SMEM_SZ (XS_OFF + XS_SZ)          // 196864

// ============================ device helpers ===============================
__device__ __forceinline__ uint32_t smem_u32(const void* p) {
    return (uint32_t)__cvta_generic_to_shared(p);
}

__device__ __forceinline__ void ldsm_x2_t(uint32_t* r, uint32_t addr) {
    asm volatile("ldmatrix.sync.aligned.m8n8.x2.trans.shared.b16 "
                 "{%0,%1}, [%2];"
                 : "=r"(r[0]), "=r"(r[1]) : "r"(addr));
}

__device__ __forceinline__ void mma16816(float* d, const uint32_t* a,
                                         uint32_t b0, uint32_t b1) {
    asm volatile("mma.sync.aligned.m16n8k16.row.col.f32.bf16.bf16.f32 "
                 "{%0,%1,%2,%3},{%4,%5,%6,%7},{%8,%9},{%0,%1,%2,%3};"
                 : "+f"(d[0]), "+f"(d[1]), "+f"(d[2]), "+f"(d[3])
                 : "r"(a[0]), "r"(a[1]), "r"(a[2]), "r"(a[3]),
                   "r"(b0), "r"(b1));
}

__device__ __forceinline__ uint32_t pack_bf2(__nv_bfloat16 a, __nv_bfloat16 b) {
    return (uint32_t)__bfloat16_as_ushort(a) |
           ((uint32_t)__bfloat16_as_ushort(b) << 16);
}

// split float pair into bf16-hi pair (returned) and bf16-lo pair (out param)
__device__ __forceinline__ uint32_t split2(float x, float y, uint32_t& lo) {
    __nv_bfloat16 xh = __float2bfloat16(x), yh = __float2bfloat16(y);
    float xl = x - __bfloat162float(xh), yl = y - __bfloat162float(yh);
    lo = pack_bf2(__float2bfloat16(xl), __float2bfloat16(yl));
    return pack_bf2(xh, yh);
}

__device__ __forceinline__ float tanh_fast(float x) {
    x = fminf(fmaxf(x, -10.0f), 10.0f);
    float e = __expf(2.0f * x);
    return __fdividef(e - 1.0f, e + 1.0f);
}

// ============================ kernel =======================================
extern "C" __global__ void __launch_bounds__(NTHR, 1)
rnn_pipe_kernel(const float* __restrict__ x,
                const float* __restrict__ W_hx,
                const float* __restrict__ W_hh,
                const float* __restrict__ W_ph,
                const float* __restrict__ b_h,
                const float* __restrict__ b_p,
                float* __restrict__ out)
{
    extern __shared__ char sm[];
    const uint32_t smu = smem_u32(sm);

    const int tid  = threadIdx.x;
    const int w    = tid >> 5;          // warp id, owns rows 32w..32w+31
    const int lane = tid & 31;
    const int g8   = lane >> 2;         // groupID 0..7
    const int tIG  = lane & 3;          // thread-in-group 0..3
    const int m0   = w * 32;
    const int c0   = blockIdx.x * BT;

    // ---- stage x: xs[n][t] fp32, coalesced float4 ----
    {
        float* xs = (float*)(sm + XS_OFF);
        #pragma unroll 1
        for (int idx = tid; idx < BT * SDIM / 4; idx += NTHR) {
            int n = idx >> 7, t4 = idx & 127;
            float4 v = *reinterpret_cast<const float4*>(
                x + (size_t)(c0 + n) * SDIM + t4 * 4);
            *reinterpret_cast<float4*>(xs + n * XROW + t4 * 4) = v;
        }
    }
    // ---- zero parity-0 h tiles of both groups (hi+lo): tiles 0,1,4,5 ----
    {
        uint4 z = {0u, 0u, 0u, 0u};
        #pragma unroll 1
        for (int idx = tid; idx < 2 * HT_SZ / 16; idx += NTHR) {
            *reinterpret_cast<uint4*>(sm + HB_OFF + idx * 16) = z;             // g0 par0
            *reinterpret_cast<uint4*>(sm + HB_OFF + 4 * HT_SZ + idx * 16) = z; // g1 par0
        }
    }

    // ---- gather W_hh fragments: hi -> regs (both m-tiles), lo -> SMEM ----
    uint32_t whi[128];                   // [mtile][kk][4]
    {
        #pragma unroll
        for (int tl = 0; tl < 2; ++tl) {
            const int rA = m0 + tl * 16 + g8;
            const int rB = rA + 8;
            const float* Wr0 = W_hh + (size_t)rA * HDIM;
            const float* Wr1 = W_hh + (size_t)rB * HDIM;
            char* wlo_base = sm + WLO_OFF +
                ((size_t)(w * 2 + tl) * 16 * 32 + lane) * 16;
            #pragma unroll
            for (int kk = 0; kk < 16; ++kk) {
                int cl = kk * 16 + 2 * tIG;
                int ch = cl + 8;
                float2 w00 = *reinterpret_cast<const float2*>(Wr0 + cl);
                float2 w10 = *reinterpret_cast<const float2*>(Wr1 + cl);
                float2 w01 = *reinterpret_cast<const float2*>(Wr0 + ch);
                float2 w11 = *reinterpret_cast<const float2*>(Wr1 + ch);
                uint4 lo;
                whi[tl * 64 + kk * 4 + 0] = split2(w00.x, w00.y, lo.x);
                whi[tl * 64 + kk * 4 + 1] = split2(w10.x, w10.y, lo.y);
                whi[tl * 64 + kk * 4 + 2] = split2(w01.x, w01.y, lo.z);
                whi[tl * 64 + kk * 4 + 3] = split2(w11.x, w11.y, lo.w);
                *reinterpret_cast<uint4*>(wlo_base + (size_t)kk * 32 * 16) = lo;
            }
        }
    }

    // epilogue constants (4 rows this thread writes)
    const int rA0 = m0 + g8, rA1 = rA0 + 8, rB0 = rA0 + 16, rB1 = rA0 + 24;
    const float wxA0 = W_hx[rA0], wxA1 = W_hx[rA1];
    const float wxB0 = W_hx[rB0], wxB1 = W_hx[rB1];
    const float bhA0 = b_h[rA0],  bhA1 = b_h[rA1];
    const float bhB0 = b_h[rB0],  bhB1 = b_h[rB1];

    // ldmatrix x2 per-thread offset within an h tile (16B rows)
    const uint32_t lm_off = (uint32_t)(((((lane >> 3) & 1) * 8) + (lane & 7)) * 16);
    const uint32_t hb_u32 = smu + HB_OFF;
    const char*    wlo_g0 = sm + WLO_OFF + ((size_t)(w * 2) * 16 * 32 + lane) * 16;
    const char*    wlo_g1 = wlo_g0 + 16 * 32 * 16;
    const float*   xs     = (const float*)(sm + XS_OFF);
    const int      cc     = 2 * tIG;

    __syncthreads();

    float acc[2][8];   // [group][mtileA 0-3 | mtileB 4-7]

    // ---- GEMM issue for (group g, parity par) into acc[g] ----
    auto issue = [&](int g, int par, float* A) {
        #pragma unroll
        for (int i = 0; i < 8; ++i) A[i] = 0.0f;
        const uint32_t hhi = hb_u32 + (uint32_t)(((g << 1) | par) << 13) + lm_off;
        const uint32_t hlo = hhi + HT_SZ;
        #pragma unroll
        for (int kk = 0; kk < 16; ++kk) {
            uint32_t bh2[2], bl2[2];
            ldsm_x2_t(bh2, hhi + (uint32_t)kk * 256);
            ldsm_x2_t(bl2, hlo + (uint32_t)kk * 256);
            uint4 wlA = *reinterpret_cast<const uint4*>(wlo_g0 + (size_t)kk * 512);
            uint4 wlB = *reinterpret_cast<const uint4*>(wlo_g1 + (size_t)kk * 512);
            uint32_t wloA[4] = {wlA.x, wlA.y, wlA.z, wlA.w};
            uint32_t wloB[4] = {wlB.x, wlB.y, wlB.z, wlB.w};
            const uint32_t* aA = whi + kk * 4;
            const uint32_t* aB = whi + 64 + kk * 4;
            mma16816(A,     aA,   bh2[0], bh2[1]);
            mma16816(A,     aA,   bl2[0], bl2[1]);
            mma16816(A,     wloA, bh2[0], bh2[1]);
            mma16816(A + 4, aB,   bh2[0], bh2[1]);
            mma16816(A + 4, aB,   bl2[0], bl2[1]);
            mma16816(A + 4, wloB, bh2[0], bh2[1]);
        }
    };

    // ---- epilogue for (group g, step t) from acc[g]: writes h_g(t+1) ----
    auto epilogue = [&](int g, int t, const float* A) {
        const float x0 = xs[(g * 8 + cc + 0) * XROW + t];
        const float x1 = xs[(g * 8 + cc + 1) * XROW + t];
        char* ohi = sm + HB_OFF + (((g << 1) | ((t & 1) ^ 1)) << 13);
        char* olo = ohi + HT_SZ;
        uint32_t hi, lo;
        hi = split2(tanh_fast(A[0] + fmaf(wxA0, x0, bhA0)),
                    tanh_fast(A[1] + fmaf(wxA0, x1, bhA0)), lo);
        *reinterpret_cast<uint32_t*>(ohi + rA0 * 16 + cc * 2) = hi;
        *reinterpret_cast<uint32_t*>(olo + rA0 * 16 + cc * 2) = lo;
        hi = split2(tanh_fast(A[2] + fmaf(wxA1, x0, bhA1)),
                    tanh_fast(A[3] + fmaf(wxA1, x1, bhA1)), lo);
        *reinterpret_cast<uint32_t*>(ohi + rA1 * 16 + cc * 2) = hi;
        *reinterpret_cast<uint32_t*>(olo + rA1 * 16 + cc * 2) = lo;
        hi = split2(tanh_fast(A[4] + fmaf(wxB0, x0, bhB0)),
                    tanh_fast(A[5] + fmaf(wxB0, x1, bhB0)), lo);
        *reinterpret_cast<uint32_t*>(ohi + rB0 * 16 + cc * 2) = hi;
        *reinterpret_cast<uint32_t*>(olo + rB0 * 16 + cc * 2) = lo;
        hi = split2(tanh_fast(A[6] + fmaf(wxB1, x0, bhB1)),
                    tanh_fast(A[7] + fmaf(wxB1, x1, bhB1)), lo);
        *reinterpret_cast<uint32_t*>(ohi + rB1 * 16 + cc * 2) = hi;
        *reinterpret_cast<uint32_t*>(olo + rB1 * 16 + cc * 2) = lo;
    };

    // ======================= pipelined phase loop =======================
    // Phase p: issue GEMM(g=p&1, t=p>>1); epilogue of phase p-1; sync.
    issue(0, 0, acc[0]);
    #pragma unroll 1
    for (int p = 1; p < 2 * SDIM; ++p) {
        const int g = p & 1;
        const int t = p >> 1;
        issue(g, t & 1, acc[g]);
        epilogue(g ^ 1, (p - 1) >> 1, acc[g ^ 1]);
        __syncthreads();
    }
    epilogue(1, SDIM - 1, acc[1]);
    __syncthreads();

    // ======================= final projection =======================
    // h(512) lives in parity-0 tiles of both groups.
    if (tid < BT * CDIM) {
        const int b = tid / CDIM, c = tid % CDIM;
        const int g = b >> 3, nl = b & 7;
        const char* hb = sm + HB_OFF + ((g << 1) << 13);
        const char* lb = hb + HT_SZ;
        float s = b_p[c];
        #pragma unroll 4
        for (int i = 0; i < HDIM; ++i) {
            float h = __bfloat162float(*reinterpret_cast<const __nv_bfloat16*>(
                          hb + i * 16 + nl * 2))
                    + __bfloat162float(*reinterpret_cast<const __nv_bfloat16*>(
                          lb + i * 16 + nl * 2));
            s += W_ph[c * HDIM + i] * h;
        }
        out[(size_t)(c0 + b) * CDIM + c] = s;
    }
}

extern "C" void kernel_launch(void* const* d_in, const int* in_sizes, int n_in,
                              void* d_out, int out_size)
{
    const float* x    = (const float*)d_in[0];
    const float* W_hx = (const float*)d_in[1];
    const float* W_hh = (const float*)d_in[2];
    const float* W_ph = (const float*)d_in[3];
    const float* b_h  = (const float*)d_in[4];
    const float* b_p  = (const float*)d_in[5];
    float* out = (float*)d_out;

    cudaFuncSetAttribute(rnn_pipe_kernel,
                         cudaFuncAttributeMaxDynamicSharedMemorySize, SMEM_SZ);
    rnn_pipe_kernel<<<NCTA, NTHR, SMEM_SZ>>>(x, W_hx, W_hh, W_ph, b_h, b_p, out);
}

// round 6
// speedup vs baseline: 1.2515x; 1.2515x over previous
#include <cuda_runtime.h>
#include <cuda_bf16.h>
#include <cstdint>

// ============================ problem constants ============================
#define HDIM 256
#define SDIM 512
#define BDIM 2048
#define CDIM 10
#define BT   16                 // batch columns per CTA (N)
#define NCTA (BDIM / BT)        // 128
#define NTHR 256                // 8 warps, each owns m=32 (two m16 tiles)

// ============================ SMEM layout (bytes) ==========================
// Wlo fragments: [8 warps][2 mtiles][16 k][32 lanes][16B] = 131072 B
#define WLO_OFF 0
#define WLO_SZ  131072
// h tiles, [k=256][n=16] bf16, row stride 48B (16B-aligned for ldmatrix):
//   hi0, lo0, hi1, lo1
#define HROW    48
#define HTILE   (HDIM * HROW)            // 12288
#define HB_OFF  WLO_SZ                   // 131072
#define HB_SZ   (4 * HTILE)              // 49152
// x staged [n=16][t=512] fp32, row pad 516 floats
#define XROW    516
#define XS_OFF  (HB_OFF + HB_SZ)         // 180224
#define XS_SZ   (BT * XROW * 4)          // 33024
#define SMEM_SZ (XS_OFF + XS_SZ)         // 213248

// ============================ device helpers ===============================
__device__ __forceinline__ uint32_t smem_u32(const void* p) {
    return (uint32_t)__cvta_generic_to_shared(p);
}

__device__ __forceinline__ void ldsm_x4_t(uint32_t* r, uint32_t addr) {
    asm volatile("ldmatrix.sync.aligned.m8n8.x4.trans.shared.b16 "
                 "{%0,%1,%2,%3}, [%4];"
                 : "=r"(r[0]), "=r"(r[1]), "=r"(r[2]), "=r"(r[3])
                 : "r"(addr));
}

__device__ __forceinline__ void mma16816(float* d, const uint32_t* a,
                                         uint32_t b0, uint32_t b1) {
    asm volatile("mma.sync.aligned.m16n8k16.row.col.f32.bf16.bf16.f32 "
                 "{%0,%1,%2,%3},{%4,%5,%6,%7},{%8,%9},{%0,%1,%2,%3};"
                 : "+f"(d[0]), "+f"(d[1]), "+f"(d[2]), "+f"(d[3])
                 : "r"(a[0]), "r"(a[1]), "r"(a[2]), "r"(a[3]),
                   "r"(b0), "r"(b1));
}

// split float pair into bf16-hi pair (returned, x in low half) and
// bf16-lo residual pair (out param). Exact residual via bit extraction.
__device__ __forceinline__ uint32_t split2(float x, float y, uint32_t& lo) {
    uint32_t hi;
    asm("cvt.rn.bf16x2.f32 %0, %1, %2;" : "=r"(hi) : "f"(y), "f"(x));
    float fx = __uint_as_float(hi << 16);
    float fy = __uint_as_float(hi & 0xffff0000u);
    float rx = x - fx, ry = y - fy;
    asm("cvt.rn.bf16x2.f32 %0, %1, %2;" : "=r"(lo) : "f"(ry), "f"(rx));
    return hi;
}

__device__ __forceinline__ float tanh_fast(float x) {
    // 1 - 2/(e^{2x}+1); inf-safe: e=inf -> 1, e=0 -> -1
    float e = __expf(2.0f * x);
    float d = e + 1.0f;
    float r;
    asm("rcp.approx.f32 %0, %1;" : "=f"(r) : "f"(d));
    return fmaf(-2.0f, r, 1.0f);
}

// ============================ kernel =======================================
extern "C" __global__ void __launch_bounds__(NTHR, 1)
rnn_hmma6_kernel(const float* __restrict__ x,
                 const float* __restrict__ W_hx,
                 const float* __restrict__ W_hh,
                 const float* __restrict__ W_ph,
                 const float* __restrict__ b_h,
                 const float* __restrict__ b_p,
                 float* __restrict__ out)
{
    extern __shared__ char sm[];
    const uint32_t smu = smem_u32(sm);

    const int tid  = threadIdx.x;
    const int w    = tid >> 5;          // warp id, owns rows 32w..32w+31
    const int lane = tid & 31;
    const int g    = lane >> 2;         // groupID 0..7
    const int tIG  = lane & 3;          // thread-in-group 0..3
    const int m0   = w * 32;
    const int c0   = blockIdx.x * BT;

    // ---- stage x: xs[n][t] fp32, coalesced float4 ----
    {
        float* xs = (float*)(sm + XS_OFF);
        #pragma unroll 1
        for (int idx = tid; idx < BT * SDIM / 4; idx += NTHR) {
            int n = idx >> 7, t4 = idx & 127;
            float4 v = *reinterpret_cast<const float4*>(
                x + (size_t)(c0 + n) * SDIM + t4 * 4);
            *reinterpret_cast<float4*>(xs + n * XROW + t4 * 4) = v;
        }
    }
    // ---- zero h buffer 0 (hi0 + lo0) ----
    {
        uint4 z = {0u, 0u, 0u, 0u};
        #pragma unroll 1
        for (int idx = tid; idx < 2 * HTILE / 16; idx += NTHR)
            *reinterpret_cast<uint4*>(sm + HB_OFF + idx * 16) = z;
    }

    // ---- gather W_hh fragments: hi -> regs (both tiles), lo -> SMEM ----
    uint32_t whi[128];                   // [mtile][kk][4]
    {
        #pragma unroll
        for (int tl = 0; tl < 2; ++tl) {
            const int rA = m0 + tl * 16 + g;
            const int rB = rA + 8;
            const float* Wr0 = W_hh + (size_t)rA * HDIM;
            const float* Wr1 = W_hh + (size_t)rB * HDIM;
            char* wlo_base = sm + WLO_OFF +
                ((size_t)(w * 2 + tl) * 16 * 32 + lane) * 16;
            #pragma unroll
            for (int kk = 0; kk < 16; ++kk) {
                int cl = kk * 16 + 2 * tIG;
                int ch = cl + 8;
                float2 w00 = *reinterpret_cast<const float2*>(Wr0 + cl);
                float2 w10 = *reinterpret_cast<const float2*>(Wr1 + cl);
                float2 w01 = *reinterpret_cast<const float2*>(Wr0 + ch);
                float2 w11 = *reinterpret_cast<const float2*>(Wr1 + ch);
                uint4 lo;
                whi[tl * 64 + kk * 4 + 0] = split2(w00.x, w00.y, lo.x);
                whi[tl * 64 + kk * 4 + 1] = split2(w10.x, w10.y, lo.y);
                whi[tl * 64 + kk * 4 + 2] = split2(w01.x, w01.y, lo.z);
                whi[tl * 64 + kk * 4 + 3] = split2(w11.x, w11.y, lo.w);
                *reinterpret_cast<uint4*>(wlo_base + (size_t)kk * 32 * 16) = lo;
            }
        }
    }

    // epilogue constants (4 rows this thread writes)
    const int rA0 = m0 + g, rA1 = rA0 + 8, rB0 = rA0 + 16, rB1 = rA0 + 24;
    const float wxA0 = W_hx[rA0], wxA1 = W_hx[rA1];
    const float wxB0 = W_hx[rB0], wxB1 = W_hx[rB1];
    const float bhA0 = b_h[rA0],  bhA1 = b_h[rA1];
    const float bhB0 = b_h[rB0],  bhB1 = b_h[rB1];

    // ldmatrix per-thread fixed offset within an h tile
    const uint32_t lm_off = (uint32_t)((((lane >> 3) & 1) * 8 + (lane & 7)) * HROW
                                       + ((lane >> 4) * 16));
    const uint32_t hb_u32 = smu + HB_OFF;
    const char* wloA_p = sm + WLO_OFF + ((size_t)(w * 2) * 16 * 32 + lane) * 16;
    const char* wloB_p = wloA_p + 16 * 32 * 16;
    const float* xs = (const float*)(sm + XS_OFF);
    const int cc = 2 * tIG;

    __syncthreads();

    // ======================= time loop =======================
    #pragma unroll 1
    for (int t = 0; t < SDIM; ++t) {
        const int p = t & 1;
        const uint32_t hhi = hb_u32 + (uint32_t)(p * 2 * HTILE) + lm_off;
        const uint32_t hlo = hhi + HTILE;

        // hoist x loads: latency hides under MMA drain
        const float x00 = xs[(cc + 0) * XROW + t];
        const float x01 = xs[(cc + 1) * XROW + t];
        const float x08 = xs[(cc + 8) * XROW + t];
        const float x09 = xs[(cc + 9) * XROW + t];

        float DA0[4] = {0.f,0.f,0.f,0.f};
        float DA1[4] = {0.f,0.f,0.f,0.f};
        float DB0[4] = {0.f,0.f,0.f,0.f};
        float DB1[4] = {0.f,0.f,0.f,0.f};

        // -------- software-pipelined k-loop (prefetch kk+1) --------
        uint32_t bhv[2][4], blv[2][4];
        uint4 wa[2], wb[2];
        ldsm_x4_t(bhv[0], hhi);
        ldsm_x4_t(blv[0], hlo);
        wa[0] = *reinterpret_cast<const uint4*>(wloA_p);
        wb[0] = *reinterpret_cast<const uint4*>(wloB_p);

        #pragma unroll
        for (int kk = 0; kk < 16; ++kk) {
            const int cu = kk & 1, nx = cu ^ 1;
            if (kk < 15) {
                ldsm_x4_t(bhv[nx], hhi + (uint32_t)(kk + 1) * (16 * HROW));
                ldsm_x4_t(blv[nx], hlo + (uint32_t)(kk + 1) * (16 * HROW));
                wa[nx] = *reinterpret_cast<const uint4*>(wloA_p + (kk + 1) * 512);
                wb[nx] = *reinterpret_cast<const uint4*>(wloB_p + (kk + 1) * 512);
            }
            uint32_t wloA[4] = {wa[cu].x, wa[cu].y, wa[cu].z, wa[cu].w};
            uint32_t wloB[4] = {wb[cu].x, wb[cu].y, wb[cu].z, wb[cu].w};
            const uint32_t* aA = whi + kk * 4;
            const uint32_t* aB = whi + 64 + kk * 4;
            const uint32_t* bh4 = bhv[cu];
            const uint32_t* bl4 = blv[cu];

            // tile 0
            mma16816(DA0, aA,   bh4[0], bh4[1]);
            mma16816(DA0, aA,   bl4[0], bl4[1]);
            mma16816(DA0, wloA, bh4[0], bh4[1]);
            mma16816(DA1, aA,   bh4[2], bh4[3]);
            mma16816(DA1, aA,   bl4[2], bl4[3]);
            mma16816(DA1, wloA, bh4[2], bh4[3]);
            // tile 1
            mma16816(DB0, aB,   bh4[0], bh4[1]);
            mma16816(DB0, aB,   bl4[0], bl4[1]);
            mma16816(DB0, wloB, bh4[0], bh4[1]);
            mma16816(DB1, aB,   bh4[2], bh4[3]);
            mma16816(DB1, aB,   bl4[2], bl4[3]);
            mma16816(DB1, wloB, bh4[2], bh4[3]);
        }

        // ---- epilogue: +Whx*x_t + b_h, tanh, hi/lo split, store to buf p^1 ----
        char* ohi = sm + HB_OFF + (p ^ 1) * 2 * HTILE;
        char* olo = ohi + HTILE;
        uint32_t hi, lo;

        hi = split2(tanh_fast(DA0[0] + fmaf(wxA0, x00, bhA0)),
                    tanh_fast(DA0[1] + fmaf(wxA0, x01, bhA0)), lo);
        *reinterpret_cast<uint32_t*>(ohi + rA0 * HROW + 4 * tIG) = hi;
        *reinterpret_cast<uint32_t*>(olo + rA0 * HROW + 4 * tIG) = lo;
        hi = split2(tanh_fast(DA0[2] + fmaf(wxA1, x00, bhA1)),
                    tanh_fast(DA0[3] + fmaf(wxA1, x01, bhA1)), lo);
        *reinterpret_cast<uint32_t*>(ohi + rA1 * HROW + 4 * tIG) = hi;
        *reinterpret_cast<uint32_t*>(olo + rA1 * HROW + 4 * tIG) = lo;
        hi = split2(tanh_fast(DA1[0] + fmaf(wxA0, x08, bhA0)),
                    tanh_fast(DA1[1] + fmaf(wxA0, x09, bhA0)), lo);
        *reinterpret_cast<uint32_t*>(ohi + rA0 * HROW + 16 + 4 * tIG) = hi;
        *reinterpret_cast<uint32_t*>(olo + rA0 * HROW + 16 + 4 * tIG) = lo;
        hi = split2(tanh_fast(DA1[2] + fmaf(wxA1, x08, bhA1)),
                    tanh_fast(DA1[3] + fmaf(wxA1, x09, bhA1)), lo);
        *reinterpret_cast<uint32_t*>(ohi + rA1 * HROW + 16 + 4 * tIG) = hi;
        *reinterpret_cast<uint32_t*>(olo + rA1 * HROW + 16 + 4 * tIG) = lo;

        hi = split2(tanh_fast(DB0[0] + fmaf(wxB0, x00, bhB0)),
                    tanh_fast(DB0[1] + fmaf(wxB0, x01, bhB0)), lo);
        *reinterpret_cast<uint32_t*>(ohi + rB0 * HROW + 4 * tIG) = hi;
        *reinterpret_cast<uint32_t*>(olo + rB0 * HROW + 4 * tIG) = lo;
        hi = split2(tanh_fast(DB0[2] + fmaf(wxB1, x00, bhB1)),
                    tanh_fast(DB0[3] + fmaf(wxB1, x01, bhB1)), lo);
        *reinterpret_cast<uint32_t*>(ohi + rB1 * HROW + 4 * tIG) = hi;
        *reinterpret_cast<uint32_t*>(olo + rB1 * HROW + 4 * tIG) = lo;
        hi = split2(tanh_fast(DB1[0] + fmaf(wxB0, x08, bhB0)),
                    tanh_fast(DB1[1] + fmaf(wxB0, x09, bhB0)), lo);
        *reinterpret_cast<uint32_t*>(ohi + rB0 * HROW + 16 + 4 * tIG) = hi;
        *reinterpret_cast<uint32_t*>(olo + rB0 * HROW + 16 + 4 * tIG) = lo;
        hi = split2(tanh_fast(DB1[2] + fmaf(wxB1, x08, bhB1)),
                    tanh_fast(DB1[3] + fmaf(wxB1, x09, bhB1)), lo);
        *reinterpret_cast<uint32_t*>(ohi + rB1 * HROW + 16 + 4 * tIG) = hi;
        *reinterpret_cast<uint32_t*>(olo + rB1 * HROW + 16 + 4 * tIG) = lo;

        __syncthreads();
    }

    // ======================= final projection =======================
    if (tid < BT * CDIM) {
        const int b = tid / CDIM, c = tid % CDIM;
        const char* hb = sm + HB_OFF;
        const char* lb = hb + HTILE;
        float s = b_p[c];
        #pragma unroll 4
        for (int i = 0; i < HDIM; ++i) {
            float h = __bfloat162float(*reinterpret_cast<const __nv_bfloat16*>(
                          hb + i * HROW + 2 * b))
                    + __bfloat162float(*reinterpret_cast<const __nv_bfloat16*>(
                          lb + i * HROW + 2 * b));
            s += W_ph[c * HDIM + i] * h;
        }
        out[(size_t)(c0 + b) * CDIM + c] = s;
    }
}

extern "C" void kernel_launch(void* const* d_in, const int* in_sizes, int n_in,
                              void* d_out, int out_size)
{
    const float* x    = (const float*)d_in[0];
    const float* W_hx = (const float*)d_in[1];
    const float* W_hh = (const float*)d_in[2];
    const float* W_ph = (const float*)d_in[3];
    const float* b_h  = (const float*)d_in[4];
    const float* b_p  = (const float*)d_in[5];
    float* out = (float*)d_out;

    cudaFuncSetAttribute(rnn_hmma6_kernel,
                         cudaFuncAttributeMaxDynamicSharedMemorySize, SMEM_SZ);
    rnn_hmma6_kernel<<<NCTA, NTHR, SMEM_SZ>>>(x, W_hx, W_hh, W_ph, b_h, b_p, out);
}